// round 4
// baseline (speedup 1.0000x reference)
#include <cuda_runtime.h>

// Problem constants
constexpr int NB  = 16;      // batch
constexpr int NS  = 1024;    // seq
constexpr int NIN = 512;     // in features
constexpr int NOUT= 512;     // out features
constexpr int NH  = 8;       // heads
constexpr int NDH = 64;      // head dim
constexpr int NM  = NB * NS; // 16384 rows

// Scratch (device globals; allocation in kernel_launch is forbidden).
// Total static scratch ~148 MB.
//   g_q/g_k/g_v : 16 MB each
//   g_E         : 64 MB  -- exp(scores) for ONE head [b][s][t]; REUSED later
//                          as the pre-LN projection output y[16384][512] (32 MB)
//   g_R         : 4 MB   -- 1/sum_b E for one head [s][t]
//   g_att       : 32 MB  -- concatenated heads [b*S+s][h*64+d]
__device__ float g_q[(size_t)NH * NB * NS * NDH];
__device__ float g_k[(size_t)NH * NB * NS * NDH];
__device__ float g_v[(size_t)NH * NB * NS * NDH];
__device__ float g_E[(size_t)NB * NS * NS];
__device__ float g_R[(size_t)NS * NS];
__device__ float g_att[(size_t)NM * NOUT];

// ---------------------------------------------------------------------------
// K1: QKV projection.  q[h,b,s,d] = sum_f x[b,s,f] * wq[h,f,d]
// GEMM M=16384, N=512 (h*64+d), K=512; grid.z picks q/k/v.
// 64x64 tile, 4x4 microtile, 256 threads.
// ---------------------------------------------------------------------------
__global__ void k_qkv(const float* __restrict__ x,
                      const float* __restrict__ wq,
                      const float* __restrict__ wk,
                      const float* __restrict__ wv) {
    __shared__ float a_s[16][68];   // [k][m]
    __shared__ float b_s[16][68];   // [k][n]
    const float* w   = blockIdx.z == 0 ? wq : (blockIdx.z == 1 ? wk : wv);
    float*       outp= blockIdx.z == 0 ? g_q : (blockIdx.z == 1 ? g_k : g_v);
    const int m0 = blockIdx.y * 64, n0 = blockIdx.x * 64;
    const int tid = threadIdx.x, tx = tid & 15, ty = tid >> 4;
    float acc[4][4] = {};

    for (int k0 = 0; k0 < NIN; k0 += 16) {
        for (int i = tid; i < 64 * 16; i += 256) {
            int mm = i >> 4, kk = i & 15;
            a_s[kk][mm] = x[(size_t)(m0 + mm) * NIN + k0 + kk];
        }
        for (int i = tid; i < 16 * 64; i += 256) {
            int kk = i >> 6, nn = i & 63;
            int n  = n0 + nn;
            b_s[kk][nn] = w[(size_t)(n >> 6) * (NIN * NDH) + (size_t)(k0 + kk) * NDH + (n & 63)];
        }
        __syncthreads();
        #pragma unroll
        for (int kk = 0; kk < 16; kk++) {
            float4 af = *(const float4*)&a_s[kk][ty * 4];
            float4 bf = *(const float4*)&b_s[kk][tx * 4];
            float a[4] = {af.x, af.y, af.z, af.w};
            float b[4] = {bf.x, bf.y, bf.z, bf.w};
            #pragma unroll
            for (int i = 0; i < 4; i++)
                #pragma unroll
                for (int j = 0; j < 4; j++)
                    acc[i][j] = fmaf(a[i], b[j], acc[i][j]);
        }
        __syncthreads();
    }
    const int h = n0 >> 6;
    #pragma unroll
    for (int i = 0; i < 4; i++) {
        int m = m0 + ty * 4 + i;
        float4 r = make_float4(acc[i][0], acc[i][1], acc[i][2], acc[i][3]);
        *(float4*)&outp[(size_t)h * ((size_t)NM * NDH) + (size_t)m * NDH + tx * 4] = r;
    }
}

// ---------------------------------------------------------------------------
// K2: scores for one head h.  E[b,s,t] = exp( (q[h,b,s,:] . k[h,b,t,:]) / 8 )
// per b: GEMM M=1024, N=1024, K=64.  64x64 tile, single K pass.
// ---------------------------------------------------------------------------
__global__ void k_scores(int h) {
    __shared__ float qs[64][68];   // [d][s]
    __shared__ float ks[64][68];   // [d][t]
    const int b  = blockIdx.z;
    const size_t base = ((size_t)h * NB + b) * NS * NDH;
    const float* qp = g_q + base;
    const float* kp = g_k + base;
    const int s0 = blockIdx.y * 64, t0 = blockIdx.x * 64;
    const int tid = threadIdx.x, tx = tid & 15, ty = tid >> 4;

    for (int i = tid; i < 4096; i += 256) {
        int r = i >> 6, d = i & 63;
        qs[d][r] = qp[(size_t)(s0 + r) * NDH + d];
        ks[d][r] = kp[(size_t)(t0 + r) * NDH + d];
    }
    __syncthreads();

    float acc[4][4] = {};
    #pragma unroll 16
    for (int d = 0; d < 64; d++) {
        float4 af = *(const float4*)&qs[d][ty * 4];
        float4 bf = *(const float4*)&ks[d][tx * 4];
        float a[4] = {af.x, af.y, af.z, af.w};
        float bb[4] = {bf.x, bf.y, bf.z, bf.w};
        #pragma unroll
        for (int i = 0; i < 4; i++)
            #pragma unroll
            for (int j = 0; j < 4; j++)
                acc[i][j] = fmaf(a[i], bb[j], acc[i][j]);
    }
    float* ep = g_E + (size_t)b * NS * NS;
    #pragma unroll
    for (int i = 0; i < 4; i++) {
        int s = s0 + ty * 4 + i;
        float4 r;
        r.x = __expf(acc[i][0] * 0.125f);
        r.y = __expf(acc[i][1] * 0.125f);
        r.z = __expf(acc[i][2] * 0.125f);
        r.w = __expf(acc[i][3] * 0.125f);
        *(float4*)&ep[(size_t)s * NS + t0 + tx * 4] = r;
    }
}

// ---------------------------------------------------------------------------
// K3: batch-axis softmax denominator for one head.  R[s,t] = 1 / sum_b E[b,s,t]
// float4-vectorized: 262144 threads, each handles 4 contiguous (s,t).
// ---------------------------------------------------------------------------
__global__ void k_bsum() {
    int idx = blockIdx.x * 256 + threadIdx.x;   // over NS*NS/4 = 262144
    const float4* ep = (const float4*)g_E + idx;
    float4 sum = make_float4(0.f, 0.f, 0.f, 0.f);
    #pragma unroll
    for (int b = 0; b < 16; b++) {
        float4 e = ep[(size_t)b * (NS * NS / 4)];
        sum.x += e.x; sum.y += e.y; sum.z += e.z; sum.w += e.w;
    }
    float4 r = make_float4(1.0f / sum.x, 1.0f / sum.y, 1.0f / sum.z, 1.0f / sum.w);
    ((float4*)g_R)[idx] = r;
}

// ---------------------------------------------------------------------------
// K4: AV for one head.  att[b,s, h*64+d] = sum_t (E[b,s,t]*R[s,t]) * v[h,b,t,d]
// per b: GEMM M=1024(s), N=64(d), K=1024(t).  64x64 tile, BK=16.
// R (4MB) and much of E (64MB) stay resident in L2.
// ---------------------------------------------------------------------------
__global__ void k_av(int h) {
    __shared__ float a_s[16][68];   // [t][s]  = E * R
    __shared__ float b_s[16][68];   // [t][d]  = v
    const int b  = blockIdx.z;
    const int s0 = blockIdx.y * 64;
    const float* ep = g_E + (size_t)b * NS * NS;
    const float* vp = g_v + ((size_t)h * NB + b) * NS * NDH;
    const int tid = threadIdx.x, tx = tid & 15, ty = tid >> 4;
    float acc[4][4] = {};

    for (int t0 = 0; t0 < NS; t0 += 16) {
        for (int i = tid; i < 1024; i += 256) {
            int ss = i >> 4, tt = i & 15;
            size_t off = (size_t)(s0 + ss) * NS + t0 + tt;
            a_s[tt][ss] = ep[off] * g_R[off];
        }
        for (int i = tid; i < 1024; i += 256) {
            int tt = i >> 6, d = i & 63;
            b_s[tt][d] = vp[(size_t)(t0 + tt) * NDH + d];
        }
        __syncthreads();
        #pragma unroll
        for (int tt = 0; tt < 16; tt++) {
            float4 af = *(const float4*)&a_s[tt][ty * 4];
            float4 bf = *(const float4*)&b_s[tt][tx * 4];
            float a[4] = {af.x, af.y, af.z, af.w};
            float bb[4] = {bf.x, bf.y, bf.z, bf.w};
            #pragma unroll
            for (int i = 0; i < 4; i++)
                #pragma unroll
                for (int j = 0; j < 4; j++)
                    acc[i][j] = fmaf(a[i], bb[j], acc[i][j]);
        }
        __syncthreads();
    }
    #pragma unroll
    for (int i = 0; i < 4; i++) {
        int s = s0 + ty * 4 + i;
        float4 r = make_float4(acc[i][0], acc[i][1], acc[i][2], acc[i][3]);
        *(float4*)&g_att[(size_t)(b * NS + s) * NOUT + h * 64 + tx * 4] = r;
    }
}

// ---------------------------------------------------------------------------
// K5: output projection.  y = att @ w_out + b_out
// GEMM M=16384, N=512, K=512.  64x64 tile, 4x4 microtile.
// y is written into g_E's storage (E is dead at this point).
// ---------------------------------------------------------------------------
__global__ void k_proj(const float* __restrict__ w, const float* __restrict__ bias) {
    __shared__ float a_s[16][68];
    __shared__ float b_s[16][68];
    const int m0 = blockIdx.y * 64, n0 = blockIdx.x * 64;
    const int tid = threadIdx.x, tx = tid & 15, ty = tid >> 4;
    float acc[4][4] = {};

    for (int k0 = 0; k0 < NOUT; k0 += 16) {
        for (int i = tid; i < 64 * 16; i += 256) {
            int mm = i >> 4, kk = i & 15;
            a_s[kk][mm] = g_att[(size_t)(m0 + mm) * NOUT + k0 + kk];
        }
        for (int i = tid; i < 16 * 64; i += 256) {
            int kk = i >> 6, nn = i & 63;
            b_s[kk][nn] = w[(size_t)(k0 + kk) * NOUT + n0 + nn];
        }
        __syncthreads();
        #pragma unroll
        for (int kk = 0; kk < 16; kk++) {
            float4 af = *(const float4*)&a_s[kk][ty * 4];
            float4 bf = *(const float4*)&b_s[kk][tx * 4];
            float a[4] = {af.x, af.y, af.z, af.w};
            float b[4] = {bf.x, bf.y, bf.z, bf.w};
            #pragma unroll
            for (int i = 0; i < 4; i++)
                #pragma unroll
                for (int j = 0; j < 4; j++)
                    acc[i][j] = fmaf(a[i], b[j], acc[i][j]);
        }
        __syncthreads();
    }
    float* yp = g_E;   // reuse: pre-LN output lives in g_E's first 32 MB
    float4 bv = *(const float4*)&bias[n0 + tx * 4];
    #pragma unroll
    for (int i = 0; i < 4; i++) {
        int m = m0 + ty * 4 + i;
        float4 r = make_float4(acc[i][0] + bv.x, acc[i][1] + bv.y,
                               acc[i][2] + bv.z, acc[i][3] + bv.w);
        *(float4*)&yp[(size_t)m * NOUT + n0 + tx * 4] = r;
    }
}

// ---------------------------------------------------------------------------
// K6: LayerNorm (over 512) + LeakyReLU(0.1).  One block (256 thr) per row.
// Reads y from g_E (aliased).
// ---------------------------------------------------------------------------
__global__ void k_ln(const float* __restrict__ gamma, const float* __restrict__ beta,
                     float* __restrict__ out) {
    const int row = blockIdx.x;
    const float* yp = g_E + (size_t)row * NOUT;
    const int tid = threadIdx.x;
    float v0 = yp[tid], v1 = yp[tid + 256];
    float s = v0 + v1, sq = v0 * v0 + v1 * v1;

    __shared__ float red[8], red2[8], stat[2];
    #pragma unroll
    for (int o = 16; o > 0; o >>= 1) {
        s  += __shfl_xor_sync(0xFFFFFFFFu, s,  o);
        sq += __shfl_xor_sync(0xFFFFFFFFu, sq, o);
    }
    int wid = tid >> 5, lane = tid & 31;
    if (lane == 0) { red[wid] = s; red2[wid] = sq; }
    __syncthreads();
    if (tid == 0) {
        float S = 0.f, Q = 0.f;
        #pragma unroll
        for (int i = 0; i < 8; i++) { S += red[i]; Q += red2[i]; }
        float mu  = S * (1.0f / NOUT);
        float var = Q * (1.0f / NOUT) - mu * mu;
        stat[0] = mu;
        stat[1] = rsqrtf(var + 1e-5f);
    }
    __syncthreads();
    float mu = stat[0], rv = stat[1];

    float t0 = (v0 - mu) * rv * gamma[tid]       + beta[tid];
    float t1 = (v1 - mu) * rv * gamma[tid + 256] + beta[tid + 256];
    t0 = t0 >= 0.f ? t0 : 0.1f * t0;
    t1 = t1 >= 0.f ? t1 : 0.1f * t1;
    out[(size_t)row * NOUT + tid]       = t0;
    out[(size_t)row * NOUT + tid + 256] = t1;
}

// ---------------------------------------------------------------------------
extern "C" void kernel_launch(void* const* d_in, const int* in_sizes, int n_in,
                              void* d_out, int out_size) {
    const float* x     = (const float*)d_in[0];
    const float* wq    = (const float*)d_in[1];
    const float* wk    = (const float*)d_in[2];
    const float* wv    = (const float*)d_in[3];
    const float* w_out = (const float*)d_in[4];
    const float* b_out = (const float*)d_in[5];
    const float* gamma = (const float*)d_in[6];
    const float* beta  = (const float*)d_in[7];
    float* out = (float*)d_out;

    k_qkv<<<dim3(NOUT / 64, NM / 64, 3), 256>>>(x, wq, wk, wv);

    for (int h = 0; h < NH; h++) {
        k_scores<<<dim3(NS / 64, NS / 64, NB), 256>>>(h);
        k_bsum  <<<(NS * NS / 4) / 256, 256>>>();
        k_av    <<<dim3(1, NS / 64, NB), 256>>>(h);
    }

    k_proj<<<dim3(NOUT / 64, NM / 64), 256>>>(w_out, b_out);
    k_ln  <<<NM, 256>>>(gamma, beta, out);
}

// round 5
// speedup vs baseline: 1.4926x; 1.4926x over previous
#include <cuda_runtime.h>

// Problem constants
constexpr int NB  = 16;      // batch
constexpr int NS  = 1024;    // seq
constexpr int NIN = 512;     // in features
constexpr int NOUT= 512;     // out features
constexpr int NH  = 8;       // heads
constexpr int NDH = 64;      // head dim
constexpr int NM  = NB * NS; // 16384 rows

// Scratch (device globals). ~148 MB total.
__device__ float g_q[(size_t)NH * NB * NS * NDH];
__device__ float g_k[(size_t)NH * NB * NS * NDH];
__device__ float g_v[(size_t)NH * NB * NS * NDH];
__device__ float g_E[(size_t)NB * NS * NS];     // one head's exp(scores); later reused as pre-LN y
__device__ float g_R[(size_t)NS * NS];          // 1/sum_b E for one head
__device__ float g_att[(size_t)NM * NOUT];      // concat heads, accumulated via atomics

// ---------------------------------------------------------------------------
// K0: zero g_att (k_av accumulates with atomicAdd)
// ---------------------------------------------------------------------------
__global__ void k_zero() {
    size_t i = (size_t)blockIdx.x * 256 + threadIdx.x;
    ((float4*)g_att)[i] = make_float4(0.f, 0.f, 0.f, 0.f);
}

// ---------------------------------------------------------------------------
// K1: QKV projection.  q[h,b,s,d] = sum_f x[b,s,f] * wq[h,f,d]
// GEMM M=16384, N=512, K=512; grid.z picks q/k/v.  64x64 tile, 4x4 micro.
// ---------------------------------------------------------------------------
__global__ void k_qkv(const float* __restrict__ x,
                      const float* __restrict__ wq,
                      const float* __restrict__ wk,
                      const float* __restrict__ wv) {
    __shared__ float a_s[16][68];   // [k][m]
    __shared__ float b_s[16][68];   // [k][n]
    const float* w   = blockIdx.z == 0 ? wq : (blockIdx.z == 1 ? wk : wv);
    float*       outp= blockIdx.z == 0 ? g_q : (blockIdx.z == 1 ? g_k : g_v);
    const int m0 = blockIdx.y * 64, n0 = blockIdx.x * 64;
    const int tid = threadIdx.x, tx = tid & 15, ty = tid >> 4;
    float acc[4][4] = {};

    for (int k0 = 0; k0 < NIN; k0 += 16) {
        for (int i = tid; i < 64 * 16; i += 256) {
            int mm = i >> 4, kk = i & 15;
            a_s[kk][mm] = x[(size_t)(m0 + mm) * NIN + k0 + kk];
        }
        for (int i = tid; i < 16 * 64; i += 256) {
            int kk = i >> 6, nn = i & 63;
            int n  = n0 + nn;
            b_s[kk][nn] = w[(size_t)(n >> 6) * (NIN * NDH) + (size_t)(k0 + kk) * NDH + (n & 63)];
        }
        __syncthreads();
        #pragma unroll
        for (int kk = 0; kk < 16; kk++) {
            float4 af = *(const float4*)&a_s[kk][ty * 4];
            float4 bf = *(const float4*)&b_s[kk][tx * 4];
            float a[4] = {af.x, af.y, af.z, af.w};
            float b[4] = {bf.x, bf.y, bf.z, bf.w};
            #pragma unroll
            for (int i = 0; i < 4; i++)
                #pragma unroll
                for (int j = 0; j < 4; j++)
                    acc[i][j] = fmaf(a[i], b[j], acc[i][j]);
        }
        __syncthreads();
    }
    const int h = n0 >> 6;
    #pragma unroll
    for (int i = 0; i < 4; i++) {
        int m = m0 + ty * 4 + i;
        float4 r = make_float4(acc[i][0], acc[i][1], acc[i][2], acc[i][3]);
        *(float4*)&outp[(size_t)h * ((size_t)NM * NDH) + (size_t)m * NDH + tx * 4] = r;
    }
}

// ---------------------------------------------------------------------------
// K2: scores for one head.  E[b,s,t] = exp( (q.k)/8 )
// 128x128 tile, 8x8 microtile, BK=16 (4 passes over d=64).
// grid (8, 8, 16) = 1024 blocks.
// ---------------------------------------------------------------------------
__global__ void __launch_bounds__(256) k_scores(int h) {
    __shared__ float qs[16][132];   // [d][s]
    __shared__ float ks[16][132];   // [d][t]
    const int b  = blockIdx.z;
    const size_t base = ((size_t)h * NB + b) * NS * NDH;
    const float* qp = g_q + base;
    const float* kp = g_k + base;
    const int s0 = blockIdx.y * 128, t0 = blockIdx.x * 128;
    const int tid = threadIdx.x, tx = tid & 15, ty = tid >> 4;
    float acc[8][8] = {};

    for (int k0 = 0; k0 < NDH; k0 += 16) {
        #pragma unroll
        for (int l = 0; l < 2; l++) {
            int r  = l * 64 + (tid >> 2);
            int cq = (tid & 3) * 4;
            float4 qv = *(const float4*)&qp[(size_t)(s0 + r) * NDH + k0 + cq];
            qs[cq + 0][r] = qv.x; qs[cq + 1][r] = qv.y;
            qs[cq + 2][r] = qv.z; qs[cq + 3][r] = qv.w;
            float4 kv = *(const float4*)&kp[(size_t)(t0 + r) * NDH + k0 + cq];
            ks[cq + 0][r] = kv.x; ks[cq + 1][r] = kv.y;
            ks[cq + 2][r] = kv.z; ks[cq + 3][r] = kv.w;
        }
        __syncthreads();
        #pragma unroll
        for (int kk = 0; kk < 16; kk++) {
            float a[8], bb[8];
            *(float4*)&a[0]  = *(const float4*)&qs[kk][ty * 8];
            *(float4*)&a[4]  = *(const float4*)&qs[kk][ty * 8 + 4];
            *(float4*)&bb[0] = *(const float4*)&ks[kk][tx * 8];
            *(float4*)&bb[4] = *(const float4*)&ks[kk][tx * 8 + 4];
            #pragma unroll
            for (int i = 0; i < 8; i++)
                #pragma unroll
                for (int j = 0; j < 8; j++)
                    acc[i][j] = fmaf(a[i], bb[j], acc[i][j]);
        }
        __syncthreads();
    }
    float* ep = g_E + (size_t)b * NS * NS;
    #pragma unroll
    for (int i = 0; i < 8; i++) {
        int s = s0 + ty * 8 + i;
        float4 r0, r1;
        r0.x = __expf(acc[i][0] * 0.125f); r0.y = __expf(acc[i][1] * 0.125f);
        r0.z = __expf(acc[i][2] * 0.125f); r0.w = __expf(acc[i][3] * 0.125f);
        r1.x = __expf(acc[i][4] * 0.125f); r1.y = __expf(acc[i][5] * 0.125f);
        r1.z = __expf(acc[i][6] * 0.125f); r1.w = __expf(acc[i][7] * 0.125f);
        *(float4*)&ep[(size_t)s * NS + t0 + tx * 8]     = r0;
        *(float4*)&ep[(size_t)s * NS + t0 + tx * 8 + 4] = r1;
    }
}

// ---------------------------------------------------------------------------
// K3: batch-axis denominator.  R[s,t] = 1 / sum_b E[b,s,t]   (float4)
// ---------------------------------------------------------------------------
__global__ void k_bsum() {
    int idx = blockIdx.x * 256 + threadIdx.x;   // over NS*NS/4
    const float4* ep = (const float4*)g_E + idx;
    float4 sum = make_float4(0.f, 0.f, 0.f, 0.f);
    #pragma unroll
    for (int b = 0; b < 16; b++) {
        float4 e = ep[(size_t)b * (NS * NS / 4)];
        sum.x += e.x; sum.y += e.y; sum.z += e.z; sum.w += e.w;
    }
    ((float4*)g_R)[idx] = make_float4(1.f / sum.x, 1.f / sum.y, 1.f / sum.z, 1.f / sum.w);
}

// ---------------------------------------------------------------------------
// K4: AV, split-K x4.  att[b,s,h*64+d] += sum_{t in chunk} (E*R)[b,s,t]*v[b,t,d]
// grid (4 t-chunks, 16 s-tiles, 16 b) = 1024 blocks.  64x64 tile, BK=16.
// Partial sums accumulated into g_att via atomicAdd.
// ---------------------------------------------------------------------------
__global__ void k_av(int h) {
    __shared__ float a_s[16][68];   // [t][s]  = E * R
    __shared__ float b_s[16][68];   // [t][d]  = v
    const int b  = blockIdx.z;
    const int s0 = blockIdx.y * 64;
    const int tb = blockIdx.x * 256;
    const float* ep = g_E + (size_t)b * NS * NS;
    const float* vp = g_v + ((size_t)h * NB + b) * NS * NDH;
    const int tid = threadIdx.x, tx = tid & 15, ty = tid >> 4;
    const int ssl = tid >> 2, tql = (tid & 3) * 4;      // E loader coords
    const int ttl = tid >> 4, d4l = (tid & 15) * 4;     // V loader coords
    float acc[4][4] = {};

    for (int t0 = tb; t0 < tb + 256; t0 += 16) {
        size_t off = (size_t)(s0 + ssl) * NS + t0 + tql;
        float4 e  = *(const float4*)&ep[off];
        float4 rr = *(const float4*)&g_R[off];
        a_s[tql + 0][ssl] = e.x * rr.x;
        a_s[tql + 1][ssl] = e.y * rr.y;
        a_s[tql + 2][ssl] = e.z * rr.z;
        a_s[tql + 3][ssl] = e.w * rr.w;
        *(float4*)&b_s[ttl][d4l] = *(const float4*)&vp[(size_t)(t0 + ttl) * NDH + d4l];
        __syncthreads();
        #pragma unroll
        for (int tt = 0; tt < 16; tt++) {
            float4 af = *(const float4*)&a_s[tt][ty * 4];
            float4 bf = *(const float4*)&b_s[tt][tx * 4];
            float a[4] = {af.x, af.y, af.z, af.w};
            float bb[4] = {bf.x, bf.y, bf.z, bf.w};
            #pragma unroll
            for (int i = 0; i < 4; i++)
                #pragma unroll
                for (int j = 0; j < 4; j++)
                    acc[i][j] = fmaf(a[i], bb[j], acc[i][j]);
        }
        __syncthreads();
    }
    #pragma unroll
    for (int i = 0; i < 4; i++) {
        int s = s0 + ty * 4 + i;
        float* dst = &g_att[(size_t)(b * NS + s) * NOUT + h * 64 + tx * 4];
        #pragma unroll
        for (int j = 0; j < 4; j++) atomicAdd(dst + j, acc[i][j]);
    }
}

// ---------------------------------------------------------------------------
// K5: output projection.  y = att @ w_out + b_out  (y aliased into g_E)
// GEMM M=16384, N=512, K=512.  64x64 tile, 4x4 micro.
// ---------------------------------------------------------------------------
__global__ void k_proj(const float* __restrict__ w, const float* __restrict__ bias) {
    __shared__ float a_s[16][68];
    __shared__ float b_s[16][68];
    const int m0 = blockIdx.y * 64, n0 = blockIdx.x * 64;
    const int tid = threadIdx.x, tx = tid & 15, ty = tid >> 4;
    float acc[4][4] = {};

    for (int k0 = 0; k0 < NOUT; k0 += 16) {
        for (int i = tid; i < 64 * 16; i += 256) {
            int mm = i >> 4, kk = i & 15;
            a_s[kk][mm] = g_att[(size_t)(m0 + mm) * NOUT + k0 + kk];
        }
        for (int i = tid; i < 16 * 64; i += 256) {
            int kk = i >> 6, nn = i & 63;
            b_s[kk][nn] = w[(size_t)(k0 + kk) * NOUT + n0 + nn];
        }
        __syncthreads();
        #pragma unroll
        for (int kk = 0; kk < 16; kk++) {
            float4 af = *(const float4*)&a_s[kk][ty * 4];
            float4 bf = *(const float4*)&b_s[kk][tx * 4];
            float a[4] = {af.x, af.y, af.z, af.w};
            float b[4] = {bf.x, bf.y, bf.z, bf.w};
            #pragma unroll
            for (int i = 0; i < 4; i++)
                #pragma unroll
                for (int j = 0; j < 4; j++)
                    acc[i][j] = fmaf(a[i], b[j], acc[i][j]);
        }
        __syncthreads();
    }
    float* yp = g_E;   // reuse g_E as pre-LN output
    float4 bv = *(const float4*)&bias[n0 + tx * 4];
    #pragma unroll
    for (int i = 0; i < 4; i++) {
        int m = m0 + ty * 4 + i;
        float4 r = make_float4(acc[i][0] + bv.x, acc[i][1] + bv.y,
                               acc[i][2] + bv.z, acc[i][3] + bv.w);
        *(float4*)&yp[(size_t)m * NOUT + n0 + tx * 4] = r;
    }
}

// ---------------------------------------------------------------------------
// K6: LayerNorm + LeakyReLU(0.1).  One block per row (reads y from g_E).
// ---------------------------------------------------------------------------
__global__ void k_ln(const float* __restrict__ gamma, const float* __restrict__ beta,
                     float* __restrict__ out) {
    const int row = blockIdx.x;
    const float* yp = g_E + (size_t)row * NOUT;
    const int tid = threadIdx.x;
    float v0 = yp[tid], v1 = yp[tid + 256];
    float s = v0 + v1, sq = v0 * v0 + v1 * v1;

    __shared__ float red[8], red2[8], stat[2];
    #pragma unroll
    for (int o = 16; o > 0; o >>= 1) {
        s  += __shfl_xor_sync(0xFFFFFFFFu, s,  o);
        sq += __shfl_xor_sync(0xFFFFFFFFu, sq, o);
    }
    int wid = tid >> 5, lane = tid & 31;
    if (lane == 0) { red[wid] = s; red2[wid] = sq; }
    __syncthreads();
    if (tid == 0) {
        float S = 0.f, Q = 0.f;
        #pragma unroll
        for (int i = 0; i < 8; i++) { S += red[i]; Q += red2[i]; }
        float mu  = S * (1.0f / NOUT);
        float var = Q * (1.0f / NOUT) - mu * mu;
        stat[0] = mu;
        stat[1] = rsqrtf(var + 1e-5f);
    }
    __syncthreads();
    float mu = stat[0], rv = stat[1];

    float t0 = (v0 - mu) * rv * gamma[tid]       + beta[tid];
    float t1 = (v1 - mu) * rv * gamma[tid + 256] + beta[tid + 256];
    t0 = t0 >= 0.f ? t0 : 0.1f * t0;
    t1 = t1 >= 0.f ? t1 : 0.1f * t1;
    out[(size_t)row * NOUT + tid]       = t0;
    out[(size_t)row * NOUT + tid + 256] = t1;
}

// ---------------------------------------------------------------------------
extern "C" void kernel_launch(void* const* d_in, const int* in_sizes, int n_in,
                              void* d_out, int out_size) {
    const float* x     = (const float*)d_in[0];
    const float* wq    = (const float*)d_in[1];
    const float* wk    = (const float*)d_in[2];
    const float* wv    = (const float*)d_in[3];
    const float* w_out = (const float*)d_in[4];
    const float* b_out = (const float*)d_in[5];
    const float* gamma = (const float*)d_in[6];
    const float* beta  = (const float*)d_in[7];
    float* out = (float*)d_out;

    k_zero<<<(NM * NOUT / 4) / 256, 256>>>();
    k_qkv <<<dim3(NOUT / 64, NM / 64, 3), 256>>>(x, wq, wk, wv);

    for (int h = 0; h < NH; h++) {
        k_scores<<<dim3(NS / 128, NS / 128, NB), 256>>>(h);
        k_bsum  <<<(NS * NS / 4) / 256, 256>>>();
        k_av    <<<dim3(4, NS / 64, NB), 256>>>(h);
    }

    k_proj<<<dim3(NOUT / 64, NM / 64), 256>>>(w_out, b_out);
    k_ln  <<<NM, 256>>>(gamma, beta, out);
}

// round 7
// speedup vs baseline: 1.8167x; 1.2172x over previous
#include <cuda_runtime.h>

// Problem constants
constexpr int NB  = 16;      // batch
constexpr int NS  = 1024;    // seq
constexpr int NIN = 512;     // in features
constexpr int NOUT= 512;     // out features
constexpr int NH  = 8;       // heads
constexpr int NDH = 64;      // head dim
constexpr int NM  = NB * NS; // 16384 rows

// Scratch (device globals). ~148 MB total.
__device__ float g_q[(size_t)NH * NB * NS * NDH];
__device__ float g_k[(size_t)NH * NB * NS * NDH];
__device__ float g_v[(size_t)NH * NB * NS * NDH];
__device__ float g_E[(size_t)NB * NS * NS];     // one head's exp(scores); later reused as pre-LN y
__device__ float g_R[(size_t)NS * NS];          // 1/sum_b E for one head
__device__ float g_att[(size_t)NM * NOUT];      // concat heads, accumulated via atomics

// ---------------------------------------------------------------------------
// K0: zero g_att (k_av accumulates with atomicAdd)
// ---------------------------------------------------------------------------
__global__ void k_zero() {
    size_t i = (size_t)blockIdx.x * 256 + threadIdx.x;
    ((float4*)g_att)[i] = make_float4(0.f, 0.f, 0.f, 0.f);
}

// ---------------------------------------------------------------------------
// K1: QKV projection.  q[h,b,s,d] = sum_f x[b,s,f] * wq[h,f,d]
// GEMM M=16384, N=512, K=512; grid.z picks q/k/v.
// 128x128 tile, 8x8 microtile, BK=16, 256 threads.  grid (4,128,3).
// ---------------------------------------------------------------------------
__global__ void __launch_bounds__(256) k_qkv(const float* __restrict__ x,
                      const float* __restrict__ wq,
                      const float* __restrict__ wk,
                      const float* __restrict__ wv) {
    __shared__ float a_s[16][132];   // [k][m]
    __shared__ float b_s[16][132];   // [k][n]
    const float* w   = blockIdx.z == 0 ? wq : (blockIdx.z == 1 ? wk : wv);
    float*       outp= blockIdx.z == 0 ? g_q : (blockIdx.z == 1 ? g_k : g_v);
    const int m0 = blockIdx.y * 128, n0 = blockIdx.x * 128;
    const int tid = threadIdx.x, tx = tid & 15, ty = tid >> 4;
    const int ar = tid >> 2, ac = (tid & 3) * 4;        // A loader
    const int bn = (tid & 31) * 4, bk = tid >> 5;       // B loader
    float acc[8][8] = {};

    for (int k0 = 0; k0 < NIN; k0 += 16) {
        #pragma unroll
        for (int l = 0; l < 2; l++) {
            int r = ar + l * 64;
            float4 v = *(const float4*)&x[(size_t)(m0 + r) * NIN + k0 + ac];
            a_s[ac + 0][r] = v.x; a_s[ac + 1][r] = v.y;
            a_s[ac + 2][r] = v.z; a_s[ac + 3][r] = v.w;
        }
        #pragma unroll
        for (int l = 0; l < 2; l++) {
            int kk = bk + l * 8;
            int n  = n0 + bn, h = n >> 6, dh = n & 63;
            *(float4*)&b_s[kk][bn] =
                *(const float4*)&w[(size_t)h * (NIN * NDH) + (size_t)(k0 + kk) * NDH + dh];
        }
        __syncthreads();
        #pragma unroll
        for (int kk = 0; kk < 16; kk++) {
            float a[8], b[8];
            *(float4*)&a[0] = *(const float4*)&a_s[kk][ty * 8];
            *(float4*)&a[4] = *(const float4*)&a_s[kk][ty * 8 + 4];
            *(float4*)&b[0] = *(const float4*)&b_s[kk][tx * 8];
            *(float4*)&b[4] = *(const float4*)&b_s[kk][tx * 8 + 4];
            #pragma unroll
            for (int i = 0; i < 8; i++)
                #pragma unroll
                for (int j = 0; j < 8; j++)
                    acc[i][j] = fmaf(a[i], b[j], acc[i][j]);
        }
        __syncthreads();
    }
    const int n = n0 + tx * 8, h = n >> 6, dh0 = n & 63;
    float* op = outp + (size_t)h * ((size_t)NM * NDH);
    #pragma unroll
    for (int i = 0; i < 8; i++) {
        int m = m0 + ty * 8 + i;
        *(float4*)&op[(size_t)m * NDH + dh0]     = *(float4*)&acc[i][0];
        *(float4*)&op[(size_t)m * NDH + dh0 + 4] = *(float4*)&acc[i][4];
    }
}

// ---------------------------------------------------------------------------
// K2: scores for one head.  E[b,s,t] = exp( (q.k)/8 )
// 128x128 tile, 8x8 microtile, BK=16.  grid (8,8,16).
// ---------------------------------------------------------------------------
__global__ void __launch_bounds__(256) k_scores(int h) {
    __shared__ float qs[16][132];   // [d][s]
    __shared__ float ks[16][132];   // [d][t]
    const int b  = blockIdx.z;
    const size_t base = ((size_t)h * NB + b) * NS * NDH;
    const float* qp = g_q + base;
    const float* kp = g_k + base;
    const int s0 = blockIdx.y * 128, t0 = blockIdx.x * 128;
    const int tid = threadIdx.x, tx = tid & 15, ty = tid >> 4;
    float acc[8][8] = {};

    for (int k0 = 0; k0 < NDH; k0 += 16) {
        #pragma unroll
        for (int l = 0; l < 2; l++) {
            int r  = l * 64 + (tid >> 2);
            int cq = (tid & 3) * 4;
            float4 qv = *(const float4*)&qp[(size_t)(s0 + r) * NDH + k0 + cq];
            qs[cq + 0][r] = qv.x; qs[cq + 1][r] = qv.y;
            qs[cq + 2][r] = qv.z; qs[cq + 3][r] = qv.w;
            float4 kv = *(const float4*)&kp[(size_t)(t0 + r) * NDH + k0 + cq];
            ks[cq + 0][r] = kv.x; ks[cq + 1][r] = kv.y;
            ks[cq + 2][r] = kv.z; ks[cq + 3][r] = kv.w;
        }
        __syncthreads();
        #pragma unroll
        for (int kk = 0; kk < 16; kk++) {
            float a[8], bb[8];
            *(float4*)&a[0]  = *(const float4*)&qs[kk][ty * 8];
            *(float4*)&a[4]  = *(const float4*)&qs[kk][ty * 8 + 4];
            *(float4*)&bb[0] = *(const float4*)&ks[kk][tx * 8];
            *(float4*)&bb[4] = *(const float4*)&ks[kk][tx * 8 + 4];
            #pragma unroll
            for (int i = 0; i < 8; i++)
                #pragma unroll
                for (int j = 0; j < 8; j++)
                    acc[i][j] = fmaf(a[i], bb[j], acc[i][j]);
        }
        __syncthreads();
    }
    float* ep = g_E + (size_t)b * NS * NS;
    #pragma unroll
    for (int i = 0; i < 8; i++) {
        int s = s0 + ty * 8 + i;
        float4 r0, r1;
        r0.x = __expf(acc[i][0] * 0.125f); r0.y = __expf(acc[i][1] * 0.125f);
        r0.z = __expf(acc[i][2] * 0.125f); r0.w = __expf(acc[i][3] * 0.125f);
        r1.x = __expf(acc[i][4] * 0.125f); r1.y = __expf(acc[i][5] * 0.125f);
        r1.z = __expf(acc[i][6] * 0.125f); r1.w = __expf(acc[i][7] * 0.125f);
        *(float4*)&ep[(size_t)s * NS + t0 + tx * 8]     = r0;
        *(float4*)&ep[(size_t)s * NS + t0 + tx * 8 + 4] = r1;
    }
}

// ---------------------------------------------------------------------------
// K3: batch-axis denominator.  R[s,t] = 1 / sum_b E[b,s,t]   (float4)
// ---------------------------------------------------------------------------
__global__ void k_bsum() {
    int idx = blockIdx.x * 256 + threadIdx.x;   // over NS*NS/4
    const float4* ep = (const float4*)g_E + idx;
    float4 sum = make_float4(0.f, 0.f, 0.f, 0.f);
    #pragma unroll
    for (int b = 0; b < 16; b++) {
        float4 e = ep[(size_t)b * (NS * NS / 4)];
        sum.x += e.x; sum.y += e.y; sum.z += e.z; sum.w += e.w;
    }
    ((float4*)g_R)[idx] = make_float4(1.f / sum.x, 1.f / sum.y, 1.f / sum.z, 1.f / sum.w);
}

// ---------------------------------------------------------------------------
// K4: AV, split-K x4.  att[b,s,h*64+d] += sum_{t in chunk} (E*R)[b,s,t]*v[b,t,d]
// grid (4 t-chunks, 8 s-tiles, 16 b) = 512 blocks.
// 128(s)x64(d) tile, 8x4 microtile, BK=16.  atomicAdd accumulation.
// ---------------------------------------------------------------------------
__global__ void __launch_bounds__(256) k_av(int h) {
    __shared__ float a_s[16][132];  // [t][s]  = E * R
    __shared__ float b_s[16][68];   // [t][d]  = v
    const int b  = blockIdx.z;
    const int s0 = blockIdx.y * 128;
    const int tb = blockIdx.x * 256;
    const float* ep = g_E + (size_t)b * NS * NS;
    const float* vp = g_v + ((size_t)h * NB + b) * NS * NDH;
    const int tid = threadIdx.x, tx = tid & 15, ty = tid >> 4;
    const int ssl = tid >> 2, tql = (tid & 3) * 4;      // E loader (2 passes of 64 s)
    const int ttl = tid >> 4, d4l = (tid & 15) * 4;     // V loader
    float acc[8][4] = {};

    for (int t0 = tb; t0 < tb + 256; t0 += 16) {
        #pragma unroll
        for (int l = 0; l < 2; l++) {
            int ss = ssl + l * 64;
            size_t off = (size_t)(s0 + ss) * NS + t0 + tql;
            float4 e  = *(const float4*)&ep[off];
            float4 rr = *(const float4*)&g_R[off];
            a_s[tql + 0][ss] = e.x * rr.x;
            a_s[tql + 1][ss] = e.y * rr.y;
            a_s[tql + 2][ss] = e.z * rr.z;
            a_s[tql + 3][ss] = e.w * rr.w;
        }
        *(float4*)&b_s[ttl][d4l] = *(const float4*)&vp[(size_t)(t0 + ttl) * NDH + d4l];
        __syncthreads();
        #pragma unroll
        for (int tt = 0; tt < 16; tt++) {
            float a[8], bb[4];
            *(float4*)&a[0]  = *(const float4*)&a_s[tt][ty * 8];
            *(float4*)&a[4]  = *(const float4*)&a_s[tt][ty * 8 + 4];
            *(float4*)&bb[0] = *(const float4*)&b_s[tt][tx * 4];
            #pragma unroll
            for (int i = 0; i < 8; i++)
                #pragma unroll
                for (int j = 0; j < 4; j++)
                    acc[i][j] = fmaf(a[i], bb[j], acc[i][j]);
        }
        __syncthreads();
    }
    #pragma unroll
    for (int i = 0; i < 8; i++) {
        int s = s0 + ty * 8 + i;
        float* dst = &g_att[(size_t)(b * NS + s) * NOUT + h * 64 + tx * 4];
        #pragma unroll
        for (int j = 0; j < 4; j++) atomicAdd(dst + j, acc[i][j]);
    }
}

// ---------------------------------------------------------------------------
// K5: output projection.  y = att @ w_out + b_out  (y aliased into g_E)
// GEMM M=16384, N=512, K=512.  128x128 tile, 8x8 microtile.  grid (4,128).
// ---------------------------------------------------------------------------
__global__ void __launch_bounds__(256) k_proj(const float* __restrict__ w,
                                              const float* __restrict__ bias) {
    __shared__ float a_s[16][132];
    __shared__ float b_s[16][132];
    const int m0 = blockIdx.y * 128, n0 = blockIdx.x * 128;
    const int tid = threadIdx.x, tx = tid & 15, ty = tid >> 4;
    const int ar = tid >> 2, ac = (tid & 3) * 4;
    const int bn = (tid & 31) * 4, bk = tid >> 5;
    float acc[8][8] = {};

    for (int k0 = 0; k0 < NOUT; k0 += 16) {
        #pragma unroll
        for (int l = 0; l < 2; l++) {
            int r = ar + l * 64;
            float4 v = *(const float4*)&g_att[(size_t)(m0 + r) * NOUT + k0 + ac];
            a_s[ac + 0][r] = v.x; a_s[ac + 1][r] = v.y;
            a_s[ac + 2][r] = v.z; a_s[ac + 3][r] = v.w;
        }
        #pragma unroll
        for (int l = 0; l < 2; l++) {
            int kk = bk + l * 8;
            *(float4*)&b_s[kk][bn] = *(const float4*)&w[(size_t)(k0 + kk) * NOUT + n0 + bn];
        }
        __syncthreads();
        #pragma unroll
        for (int kk = 0; kk < 16; kk++) {
            float a[8], b[8];
            *(float4*)&a[0] = *(const float4*)&a_s[kk][ty * 8];
            *(float4*)&a[4] = *(const float4*)&a_s[kk][ty * 8 + 4];
            *(float4*)&b[0] = *(const float4*)&b_s[kk][tx * 8];
            *(float4*)&b[4] = *(const float4*)&b_s[kk][tx * 8 + 4];
            #pragma unroll
            for (int i = 0; i < 8; i++)
                #pragma unroll
                for (int j = 0; j < 8; j++)
                    acc[i][j] = fmaf(a[i], b[j], acc[i][j]);
        }
        __syncthreads();
    }
    float* yp = g_E;   // reuse g_E as pre-LN output
    float4 bv0 = *(const float4*)&bias[n0 + tx * 8];
    float4 bv1 = *(const float4*)&bias[n0 + tx * 8 + 4];
    #pragma unroll
    for (int i = 0; i < 8; i++) {
        int m = m0 + ty * 8 + i;
        float4 r0 = make_float4(acc[i][0] + bv0.x, acc[i][1] + bv0.y,
                                acc[i][2] + bv0.z, acc[i][3] + bv0.w);
        float4 r1 = make_float4(acc[i][4] + bv1.x, acc[i][5] + bv1.y,
                                acc[i][6] + bv1.z, acc[i][7] + bv1.w);
        *(float4*)&yp[(size_t)m * NOUT + n0 + tx * 8]     = r0;
        *(float4*)&yp[(size_t)m * NOUT + n0 + tx * 8 + 4] = r1;
    }
}

// ---------------------------------------------------------------------------
// K6: LayerNorm + LeakyReLU(0.1).  One block per row (reads y from g_E).
// ---------------------------------------------------------------------------
__global__ void k_ln(const float* __restrict__ gamma, const float* __restrict__ beta,
                     float* __restrict__ out) {
    const int row = blockIdx.x;
    const float* yp = g_E + (size_t)row * NOUT;
    const int tid = threadIdx.x;
    float v0 = yp[tid], v1 = yp[tid + 256];
    float s = v0 + v1, sq = v0 * v0 + v1 * v1;

    __shared__ float red[8], red2[8], stat[2];
    #pragma unroll
    for (int o = 16; o > 0; o >>= 1) {
        s  += __shfl_xor_sync(0xFFFFFFFFu, s,  o);
        sq += __shfl_xor_sync(0xFFFFFFFFu, sq, o);
    }
    int wid = tid >> 5, lane = tid & 31;
    if (lane == 0) { red[wid] = s; red2[wid] = sq; }
    __syncthreads();
    if (tid == 0) {
        float S = 0.f, Q = 0.f;
        #pragma unroll
        for (int i = 0; i < 8; i++) { S += red[i]; Q += red2[i]; }
        float mu  = S * (1.0f / NOUT);
        float var = Q * (1.0f / NOUT) - mu * mu;
        stat[0] = mu;
        stat[1] = rsqrtf(var + 1e-5f);
    }
    __syncthreads();
    float mu = stat[0], rv = stat[1];

    float t0 = (v0 - mu) * rv * gamma[tid]       + beta[tid];
    float t1 = (v1 - mu) * rv * gamma[tid + 256] + beta[tid + 256];
    t0 = t0 >= 0.f ? t0 : 0.1f * t0;
    t1 = t1 >= 0.f ? t1 : 0.1f * t1;
    out[(size_t)row * NOUT + tid]       = t0;
    out[(size_t)row * NOUT + tid + 256] = t1;
}

// ---------------------------------------------------------------------------
extern "C" void kernel_launch(void* const* d_in, const int* in_sizes, int n_in,
                              void* d_out, int out_size) {
    const float* x     = (const float*)d_in[0];
    const float* wq    = (const float*)d_in[1];
    const float* wk    = (const float*)d_in[2];
    const float* wv    = (const float*)d_in[3];
    const float* w_out = (const float*)d_in[4];
    const float* b_out = (const float*)d_in[5];
    const float* gamma = (const float*)d_in[6];
    const float* beta  = (const float*)d_in[7];
    float* out = (float*)d_out;

    k_zero<<<(NM * NOUT / 4) / 256, 256>>>();
    k_qkv <<<dim3(NOUT / 128, NM / 128, 3), 256>>>(x, wq, wk, wv);

    for (int h = 0; h < NH; h++) {
        k_scores<<<dim3(NS / 128, NS / 128, NB), 256>>>(h);
        k_bsum  <<<(NS * NS / 4) / 256, 256>>>();
        k_av    <<<dim3(4, NS / 128, NB), 256>>>(h);
    }

    k_proj<<<dim3(NOUT / 128, NM / 128), 256>>>(w_out, b_out);
    k_ln  <<<NM, 256>>>(gamma, beta, out);
}

// round 8
// speedup vs baseline: 1.8200x; 1.0018x over previous
#include <cuda_runtime.h>

// Problem constants
constexpr int NB  = 16;      // batch
constexpr int NS  = 1024;    // seq
constexpr int NIN = 512;     // in features
constexpr int NOUT= 512;     // out features
constexpr int NH  = 8;       // heads
constexpr int NDH = 64;      // head dim
constexpr int NM  = NB * NS; // 16384 rows

// Scratch (device globals). ~148 MB total.
__device__ float g_q[(size_t)NH * NB * NS * NDH];
__device__ float g_k[(size_t)NH * NB * NS * NDH];
__device__ float g_v[(size_t)NH * NB * NS * NDH];
__device__ float g_E[(size_t)NB * NS * NS];     // one head's exp(scores); later reused as pre-LN y
__device__ float g_R[(size_t)NS * NS];          // 1/sum_b E for one head
__device__ float g_att[(size_t)NM * NOUT];      // concat heads, accumulated via atomics

// ---- packed f32x2 helpers (Blackwell FFMA2) --------------------------------
__device__ __forceinline__ unsigned long long pack2(float x, float y) {
    unsigned long long r;
    asm("mov.b64 %0, {%1, %2};" : "=l"(r) : "f"(x), "f"(y));
    return r;
}
__device__ __forceinline__ void ffma2(unsigned long long& d,
                                      unsigned long long a, unsigned long long b) {
    asm("fma.rn.f32x2 %0, %1, %2, %0;" : "+l"(d) : "l"(a), "l"(b));
}
__device__ __forceinline__ float2 unpack2(unsigned long long v) {
    float2 f;
    asm("mov.b64 {%0, %1}, %2;" : "=f"(f.x), "=f"(f.y) : "l"(v));
    return f;
}

// ---------------------------------------------------------------------------
// K0: zero g_att (k_av accumulates with atomicAdd)
// ---------------------------------------------------------------------------
__global__ void k_zero() {
    size_t i = (size_t)blockIdx.x * 256 + threadIdx.x;
    ((float4*)g_att)[i] = make_float4(0.f, 0.f, 0.f, 0.f);
}

// ---------------------------------------------------------------------------
// K1: QKV projection.  q[h,b,s,d] = sum_f x[b,s,f] * wq[h,f,d]
// GEMM M=16384, N=512, K=512; grid.z picks q/k/v.
// 128x128 tile, 8x8 microtile (f32x2), BK=16, 256 threads.  grid (4,128,3).
// ---------------------------------------------------------------------------
__global__ void __launch_bounds__(256) k_qkv(const float* __restrict__ x,
                      const float* __restrict__ wq,
                      const float* __restrict__ wk,
                      const float* __restrict__ wv) {
    __shared__ float a_s[16][132];   // [k][m]
    __shared__ float b_s[16][132];   // [k][n]
    const float* w   = blockIdx.z == 0 ? wq : (blockIdx.z == 1 ? wk : wv);
    float*       outp= blockIdx.z == 0 ? g_q : (blockIdx.z == 1 ? g_k : g_v);
    const int m0 = blockIdx.y * 128, n0 = blockIdx.x * 128;
    const int tid = threadIdx.x, tx = tid & 15, ty = tid >> 4;
    const int ar = tid >> 2, ac = (tid & 3) * 4;        // A loader
    const int bn = (tid & 31) * 4, bk = tid >> 5;       // B loader
    unsigned long long acc2[8][4] = {};

    for (int k0 = 0; k0 < NIN; k0 += 16) {
        #pragma unroll
        for (int l = 0; l < 2; l++) {
            int r = ar + l * 64;
            float4 v = *(const float4*)&x[(size_t)(m0 + r) * NIN + k0 + ac];
            a_s[ac + 0][r] = v.x; a_s[ac + 1][r] = v.y;
            a_s[ac + 2][r] = v.z; a_s[ac + 3][r] = v.w;
        }
        #pragma unroll
        for (int l = 0; l < 2; l++) {
            int kk = bk + l * 8;
            int n  = n0 + bn, h = n >> 6, dh = n & 63;
            *(float4*)&b_s[kk][bn] =
                *(const float4*)&w[(size_t)h * (NIN * NDH) + (size_t)(k0 + kk) * NDH + dh];
        }
        __syncthreads();
        #pragma unroll
        for (int kk = 0; kk < 16; kk++) {
            float a[8];
            *(float4*)&a[0] = *(const float4*)&a_s[kk][ty * 8];
            *(float4*)&a[4] = *(const float4*)&a_s[kk][ty * 8 + 4];
            unsigned long long b2[4];
            #pragma unroll
            for (int j = 0; j < 4; j++)
                b2[j] = *(const unsigned long long*)&b_s[kk][tx * 8 + 2 * j];
            #pragma unroll
            for (int i = 0; i < 8; i++) {
                unsigned long long a2 = pack2(a[i], a[i]);
                #pragma unroll
                for (int j = 0; j < 4; j++) ffma2(acc2[i][j], a2, b2[j]);
            }
        }
        __syncthreads();
    }
    const int n = n0 + tx * 8, h = n >> 6, dh0 = n & 63;
    float* op = outp + (size_t)h * ((size_t)NM * NDH);
    #pragma unroll
    for (int i = 0; i < 8; i++) {
        int m = m0 + ty * 8 + i;
        float r[8];
        #pragma unroll
        for (int j = 0; j < 4; j++) {
            float2 p = unpack2(acc2[i][j]);
            r[2 * j] = p.x; r[2 * j + 1] = p.y;
        }
        *(float4*)&op[(size_t)m * NDH + dh0]     = *(float4*)&r[0];
        *(float4*)&op[(size_t)m * NDH + dh0 + 4] = *(float4*)&r[4];
    }
}

// ---------------------------------------------------------------------------
// K2: scores for one head.  E[b,s,t] = exp( (q.k)/8 )
// 128x128 tile, 8x8 microtile (f32x2), BK=16.  grid (8,8,16).
// ---------------------------------------------------------------------------
__global__ void __launch_bounds__(256) k_scores(int h) {
    __shared__ float qs[16][132];   // [d][s]
    __shared__ float ks[16][132];   // [d][t]
    const int b  = blockIdx.z;
    const size_t base = ((size_t)h * NB + b) * NS * NDH;
    const float* qp = g_q + base;
    const float* kp = g_k + base;
    const int s0 = blockIdx.y * 128, t0 = blockIdx.x * 128;
    const int tid = threadIdx.x, tx = tid & 15, ty = tid >> 4;
    unsigned long long acc2[8][4] = {};

    for (int k0 = 0; k0 < NDH; k0 += 16) {
        #pragma unroll
        for (int l = 0; l < 2; l++) {
            int r  = l * 64 + (tid >> 2);
            int cq = (tid & 3) * 4;
            float4 qv = *(const float4*)&qp[(size_t)(s0 + r) * NDH + k0 + cq];
            qs[cq + 0][r] = qv.x; qs[cq + 1][r] = qv.y;
            qs[cq + 2][r] = qv.z; qs[cq + 3][r] = qv.w;
            float4 kv = *(const float4*)&kp[(size_t)(t0 + r) * NDH + k0 + cq];
            ks[cq + 0][r] = kv.x; ks[cq + 1][r] = kv.y;
            ks[cq + 2][r] = kv.z; ks[cq + 3][r] = kv.w;
        }
        __syncthreads();
        #pragma unroll
        for (int kk = 0; kk < 16; kk++) {
            float a[8];
            *(float4*)&a[0] = *(const float4*)&qs[kk][ty * 8];
            *(float4*)&a[4] = *(const float4*)&qs[kk][ty * 8 + 4];
            unsigned long long b2[4];
            #pragma unroll
            for (int j = 0; j < 4; j++)
                b2[j] = *(const unsigned long long*)&ks[kk][tx * 8 + 2 * j];
            #pragma unroll
            for (int i = 0; i < 8; i++) {
                unsigned long long a2 = pack2(a[i], a[i]);
                #pragma unroll
                for (int j = 0; j < 4; j++) ffma2(acc2[i][j], a2, b2[j]);
            }
        }
        __syncthreads();
    }
    float* ep = g_E + (size_t)b * NS * NS;
    #pragma unroll
    for (int i = 0; i < 8; i++) {
        int s = s0 + ty * 8 + i;
        float e[8];
        #pragma unroll
        for (int j = 0; j < 4; j++) {
            float2 p = unpack2(acc2[i][j]);
            e[2 * j]     = __expf(p.x * 0.125f);
            e[2 * j + 1] = __expf(p.y * 0.125f);
        }
        *(float4*)&ep[(size_t)s * NS + t0 + tx * 8]     = *(float4*)&e[0];
        *(float4*)&ep[(size_t)s * NS + t0 + tx * 8 + 4] = *(float4*)&e[4];
    }
}

// ---------------------------------------------------------------------------
// K3: batch-axis denominator.  R[s,t] = 1 / sum_b E[b,s,t]   (float4)
// ---------------------------------------------------------------------------
__global__ void k_bsum() {
    int idx = blockIdx.x * 256 + threadIdx.x;   // over NS*NS/4
    const float4* ep = (const float4*)g_E + idx;
    float4 sum = make_float4(0.f, 0.f, 0.f, 0.f);
    #pragma unroll
    for (int b = 0; b < 16; b++) {
        float4 e = ep[(size_t)b * (NS * NS / 4)];
        sum.x += e.x; sum.y += e.y; sum.z += e.z; sum.w += e.w;
    }
    ((float4*)g_R)[idx] = make_float4(1.f / sum.x, 1.f / sum.y, 1.f / sum.z, 1.f / sum.w);
}

// ---------------------------------------------------------------------------
// K4: AV, split-K x4.  att[b,s,h*64+d] += sum_{t in chunk} (E*R)[b,s,t]*v[b,t,d]
// grid (4 t-chunks, 8 s-tiles, 16 b) = 512 blocks.
// 128(s)x64(d) tile, 8x4 microtile (f32x2), BK=16.  atomicAdd accumulation.
// ---------------------------------------------------------------------------
__global__ void __launch_bounds__(256) k_av(int h) {
    __shared__ float a_s[16][132];  // [t][s]  = E * R
    __shared__ float b_s[16][68];   // [t][d]  = v
    const int b  = blockIdx.z;
    const int s0 = blockIdx.y * 128;
    const int tb = blockIdx.x * 256;
    const float* ep = g_E + (size_t)b * NS * NS;
    const float* vp = g_v + ((size_t)h * NB + b) * NS * NDH;
    const int tid = threadIdx.x, tx = tid & 15, ty = tid >> 4;
    const int ssl = tid >> 2, tql = (tid & 3) * 4;      // E loader (2 passes of 64 s)
    const int ttl = tid >> 4, d4l = (tid & 15) * 4;     // V loader
    unsigned long long acc2[8][2] = {};

    for (int t0 = tb; t0 < tb + 256; t0 += 16) {
        #pragma unroll
        for (int l = 0; l < 2; l++) {
            int ss = ssl + l * 64;
            size_t off = (size_t)(s0 + ss) * NS + t0 + tql;
            float4 e  = *(const float4*)&ep[off];
            float4 rr = *(const float4*)&g_R[off];
            a_s[tql + 0][ss] = e.x * rr.x;
            a_s[tql + 1][ss] = e.y * rr.y;
            a_s[tql + 2][ss] = e.z * rr.z;
            a_s[tql + 3][ss] = e.w * rr.w;
        }
        *(float4*)&b_s[ttl][d4l] = *(const float4*)&vp[(size_t)(t0 + ttl) * NDH + d4l];
        __syncthreads();
        #pragma unroll
        for (int tt = 0; tt < 16; tt++) {
            float a[8];
            *(float4*)&a[0] = *(const float4*)&a_s[tt][ty * 8];
            *(float4*)&a[4] = *(const float4*)&a_s[tt][ty * 8 + 4];
            unsigned long long b2[2];
            #pragma unroll
            for (int j = 0; j < 2; j++)
                b2[j] = *(const unsigned long long*)&b_s[tt][tx * 4 + 2 * j];
            #pragma unroll
            for (int i = 0; i < 8; i++) {
                unsigned long long a2 = pack2(a[i], a[i]);
                #pragma unroll
                for (int j = 0; j < 2; j++) ffma2(acc2[i][j], a2, b2[j]);
            }
        }
        __syncthreads();
    }
    #pragma unroll
    for (int i = 0; i < 8; i++) {
        int s = s0 + ty * 8 + i;
        float* dst = &g_att[(size_t)(b * NS + s) * NOUT + h * 64 + tx * 4];
        float2 p0 = unpack2(acc2[i][0]);
        float2 p1 = unpack2(acc2[i][1]);
        atomicAdd(dst + 0, p0.x);
        atomicAdd(dst + 1, p0.y);
        atomicAdd(dst + 2, p1.x);
        atomicAdd(dst + 3, p1.y);
    }
}

// ---------------------------------------------------------------------------
// K5: output projection.  y = att @ w_out + b_out  (y aliased into g_E)
// GEMM M=16384, N=512, K=512.  128x128 tile, 8x8 microtile (f32x2).
// ---------------------------------------------------------------------------
__global__ void __launch_bounds__(256) k_proj(const float* __restrict__ w,
                                              const float* __restrict__ bias) {
    __shared__ float a_s[16][132];
    __shared__ float b_s[16][132];
    const int m0 = blockIdx.y * 128, n0 = blockIdx.x * 128;
    const int tid = threadIdx.x, tx = tid & 15, ty = tid >> 4;
    const int ar = tid >> 2, ac = (tid & 3) * 4;
    const int bn = (tid & 31) * 4, bk = tid >> 5;
    unsigned long long acc2[8][4] = {};

    for (int k0 = 0; k0 < NOUT; k0 += 16) {
        #pragma unroll
        for (int l = 0; l < 2; l++) {
            int r = ar + l * 64;
            float4 v = *(const float4*)&g_att[(size_t)(m0 + r) * NOUT + k0 + ac];
            a_s[ac + 0][r] = v.x; a_s[ac + 1][r] = v.y;
            a_s[ac + 2][r] = v.z; a_s[ac + 3][r] = v.w;
        }
        #pragma unroll
        for (int l = 0; l < 2; l++) {
            int kk = bk + l * 8;
            *(float4*)&b_s[kk][bn] = *(const float4*)&w[(size_t)(k0 + kk) * NOUT + n0 + bn];
        }
        __syncthreads();
        #pragma unroll
        for (int kk = 0; kk < 16; kk++) {
            float a[8];
            *(float4*)&a[0] = *(const float4*)&a_s[kk][ty * 8];
            *(float4*)&a[4] = *(const float4*)&a_s[kk][ty * 8 + 4];
            unsigned long long b2[4];
            #pragma unroll
            for (int j = 0; j < 4; j++)
                b2[j] = *(const unsigned long long*)&b_s[kk][tx * 8 + 2 * j];
            #pragma unroll
            for (int i = 0; i < 8; i++) {
                unsigned long long a2 = pack2(a[i], a[i]);
                #pragma unroll
                for (int j = 0; j < 4; j++) ffma2(acc2[i][j], a2, b2[j]);
            }
        }
        __syncthreads();
    }
    float* yp = g_E;   // reuse g_E as pre-LN output
    float bv[8];
    *(float4*)&bv[0] = *(const float4*)&bias[n0 + tx * 8];
    *(float4*)&bv[4] = *(const float4*)&bias[n0 + tx * 8 + 4];
    #pragma unroll
    for (int i = 0; i < 8; i++) {
        int m = m0 + ty * 8 + i;
        float r[8];
        #pragma unroll
        for (int j = 0; j < 4; j++) {
            float2 p = unpack2(acc2[i][j]);
            r[2 * j]     = p.x + bv[2 * j];
            r[2 * j + 1] = p.y + bv[2 * j + 1];
        }
        *(float4*)&yp[(size_t)m * NOUT + n0 + tx * 8]     = *(float4*)&r[0];
        *(float4*)&yp[(size_t)m * NOUT + n0 + tx * 8 + 4] = *(float4*)&r[4];
    }
}

// ---------------------------------------------------------------------------
// K6: LayerNorm + LeakyReLU(0.1).  One block per row (reads y from g_E).
// ---------------------------------------------------------------------------
__global__ void k_ln(const float* __restrict__ gamma, const float* __restrict__ beta,
                     float* __restrict__ out) {
    const int row = blockIdx.x;
    const float* yp = g_E + (size_t)row * NOUT;
    const int tid = threadIdx.x;
    float v0 = yp[tid], v1 = yp[tid + 256];
    float s = v0 + v1, sq = v0 * v0 + v1 * v1;

    __shared__ float red[8], red2[8], stat[2];
    #pragma unroll
    for (int o = 16; o > 0; o >>= 1) {
        s  += __shfl_xor_sync(0xFFFFFFFFu, s,  o);
        sq += __shfl_xor_sync(0xFFFFFFFFu, sq, o);
    }
    int wid = tid >> 5, lane = tid & 31;
    if (lane == 0) { red[wid] = s; red2[wid] = sq; }
    __syncthreads();
    if (tid == 0) {
        float S = 0.f, Q = 0.f;
        #pragma unroll
        for (int i = 0; i < 8; i++) { S += red[i]; Q += red2[i]; }
        float mu  = S * (1.0f / NOUT);
        float var = Q * (1.0f / NOUT) - mu * mu;
        stat[0] = mu;
        stat[1] = rsqrtf(var + 1e-5f);
    }
    __syncthreads();
    float mu = stat[0], rv = stat[1];

    float t0 = (v0 - mu) * rv * gamma[tid]       + beta[tid];
    float t1 = (v1 - mu) * rv * gamma[tid + 256] + beta[tid + 256];
    t0 = t0 >= 0.f ? t0 : 0.1f * t0;
    t1 = t1 >= 0.f ? t1 : 0.1f * t1;
    out[(size_t)row * NOUT + tid]       = t0;
    out[(size_t)row * NOUT + tid + 256] = t1;
}

// ---------------------------------------------------------------------------
extern "C" void kernel_launch(void* const* d_in, const int* in_sizes, int n_in,
                              void* d_out, int out_size) {
    const float* x     = (const float*)d_in[0];
    const float* wq    = (const float*)d_in[1];
    const float* wk    = (const float*)d_in[2];
    const float* wv    = (const float*)d_in[3];
    const float* w_out = (const float*)d_in[4];
    const float* b_out = (const float*)d_in[5];
    const float* gamma = (const float*)d_in[6];
    const float* beta  = (const float*)d_in[7];
    float* out = (float*)d_out;

    k_zero<<<(NM * NOUT / 4) / 256, 256>>>();
    k_qkv <<<dim3(NOUT / 128, NM / 128, 3), 256>>>(x, wq, wk, wv);

    for (int h = 0; h < NH; h++) {
        k_scores<<<dim3(NS / 128, NS / 128, NB), 256>>>(h);
        k_bsum  <<<(NS * NS / 4) / 256, 256>>>();
        k_av    <<<dim3(4, NS / 128, NB), 256>>>(h);
    }

    k_proj<<<dim3(NOUT / 128, NM / 128), 256>>>(w_out, b_out);
    k_ln  <<<NM, 256>>>(gamma, beta, out);
}

// round 9
// speedup vs baseline: 4.1762x; 2.2946x over previous
#include <cuda_runtime.h>
#include <cstdint>

// Problem constants
constexpr int NB  = 16;      // batch
constexpr int NS  = 1024;    // seq
constexpr int NIN = 512;     // in features
constexpr int NOUT= 512;     // out features
constexpr int NH  = 8;       // heads
constexpr int NDH = 64;      // head dim
constexpr int NM  = NB * NS; // 16384 rows

// Scratch (device globals). ~148 MB total.
__device__ float g_q[(size_t)NH * NB * NS * NDH];
__device__ float g_k[(size_t)NH * NB * NS * NDH];
__device__ float g_v[(size_t)NH * NB * NS * NDH];
__device__ float g_E[(size_t)NB * NS * NS];     // one head's exp(scores); later reused as pre-LN y
__device__ float g_R[(size_t)NS * NS];          // 1/sum_b E for one head
__device__ float g_att[(size_t)NM * NOUT];      // concat heads, accumulated via atomics

// ---- tf32 mma.sync helpers -------------------------------------------------
__device__ __forceinline__ uint32_t cvt_tf32(float x) {
    uint32_t r;
    asm("cvt.rna.tf32.f32 %0, %1;" : "=r"(r) : "f"(x));
    return r;
}
// D(16x8,f32) += A(16x8,tf32,row) * B(8x8,tf32,col)
__device__ __forceinline__ void mma8(float* c, const uint32_t* a, const uint32_t* b) {
    asm("mma.sync.aligned.m16n8k8.row.col.f32.tf32.tf32.f32 "
        "{%0,%1,%2,%3}, {%4,%5,%6,%7}, {%8,%9}, {%0,%1,%2,%3};"
        : "+f"(c[0]), "+f"(c[1]), "+f"(c[2]), "+f"(c[3])
        : "r"(a[0]), "r"(a[1]), "r"(a[2]), "r"(a[3]), "r"(b[0]), "r"(b[1]));
}
// A fragment from As[row][k] layout, ld=36  (banks: 4*(lane>>2)+(lane&3), conflict-free)
__device__ __forceinline__ void ldA36(uint32_t* a, const uint32_t* As, int row0, int ks, int lane) {
    const uint32_t* p = As + (row0 + (lane >> 2)) * 36 + ks + (lane & 3);
    a[0] = p[0]; a[1] = p[8 * 36]; a[2] = p[4]; a[3] = p[8 * 36 + 4];
}
// B fragment from Bs[n][k] layout, ld=36
__device__ __forceinline__ void ldBnk36(uint32_t* b, const uint32_t* Bs, int n0, int ks, int lane) {
    const uint32_t* p = Bs + (n0 + (lane >> 2)) * 36 + ks + (lane & 3);
    b[0] = p[0]; b[1] = p[4];
}
// B fragment from Bs[k][n] layout, ld=ldn (ldn % 32 == 4)
__device__ __forceinline__ void ldBkn(uint32_t* b, const uint32_t* Bs, int ldn, int n0, int ks, int lane) {
    const uint32_t* p = Bs + (ks + (lane & 3)) * ldn + n0 + (lane >> 2);
    b[0] = p[0]; b[1] = p[4 * ldn];
}

// ---------------------------------------------------------------------------
// K0: zero g_att (k_av accumulates with atomicAdd)
// ---------------------------------------------------------------------------
__global__ void k_zero() {
    size_t i = (size_t)blockIdx.x * 256 + threadIdx.x;
    ((float4*)g_att)[i] = make_float4(0.f, 0.f, 0.f, 0.f);
}

// ---------------------------------------------------------------------------
// K1: QKV projection (tf32 mma).  q[h,b,s,d] = sum_f x[b,s,f] * wq[h,f,d]
// GEMM M=16384, N=512, K=512.  Block 128x128, BK=32, 8 warps (2m x 4n),
// warp tile 64x32.  grid (4,128,3).
// ---------------------------------------------------------------------------
__global__ void __launch_bounds__(256) k_qkv(const float* __restrict__ x,
                      const float* __restrict__ wq,
                      const float* __restrict__ wk,
                      const float* __restrict__ wv) {
    __shared__ __align__(16) uint32_t As[128 * 36];   // x tile  [m][k]
    __shared__ __align__(16) uint32_t Bs[32 * 132];   // w tile  [k][n]
    const float* w   = blockIdx.z == 0 ? wq : (blockIdx.z == 1 ? wk : wv);
    float*      outp = blockIdx.z == 0 ? g_q : (blockIdx.z == 1 ? g_k : g_v);
    const int m0 = blockIdx.y * 128, n0 = blockIdx.x * 128;
    const int tid = threadIdx.x, lane = tid & 31, wid = tid >> 5;
    const int warp_m = (wid & 1) * 64, warp_n = (wid >> 1) * 32;
    const int xm = tid >> 3, xk = (tid & 7) * 4;
    const int n4 = tid & 31, kw = tid >> 5;
    float c[4][4][4] = {};

    for (int k0 = 0; k0 < NIN; k0 += 32) {
        #pragma unroll
        for (int l = 0; l < 4; l++) {
            int m = xm + l * 32;
            float4 v = *(const float4*)&x[(size_t)(m0 + m) * NIN + k0 + xk];
            uint4 u = make_uint4(cvt_tf32(v.x), cvt_tf32(v.y), cvt_tf32(v.z), cvt_tf32(v.w));
            *(uint4*)&As[m * 36 + xk] = u;
        }
        {
            int gn = n0 + n4 * 4, h = gn >> 6, dh = gn & 63;
            #pragma unroll
            for (int l = 0; l < 4; l++) {
                int kk = kw + l * 8;
                float4 v = *(const float4*)&w[(size_t)h * (NIN * NDH) + (size_t)(k0 + kk) * NDH + dh];
                uint4 u = make_uint4(cvt_tf32(v.x), cvt_tf32(v.y), cvt_tf32(v.z), cvt_tf32(v.w));
                *(uint4*)&Bs[kk * 132 + n4 * 4] = u;
            }
        }
        __syncthreads();
        #pragma unroll
        for (int ks = 0; ks < 32; ks += 8) {
            uint32_t a[4][4], b[4][2];
            #pragma unroll
            for (int mt = 0; mt < 4; mt++) ldA36(a[mt], As, warp_m + mt * 16, ks, lane);
            #pragma unroll
            for (int nt = 0; nt < 4; nt++) ldBkn(b[nt], Bs, 132, warp_n + nt * 8, ks, lane);
            #pragma unroll
            for (int mt = 0; mt < 4; mt++)
                #pragma unroll
                for (int nt = 0; nt < 4; nt++) mma8(c[mt][nt], a[mt], b[nt]);
        }
        __syncthreads();
    }
    #pragma unroll
    for (int mt = 0; mt < 4; mt++) {
        #pragma unroll
        for (int nt = 0; nt < 4; nt++) {
            int m = m0 + warp_m + mt * 16 + (lane >> 2);
            int n = n0 + warp_n + nt * 8 + 2 * (lane & 3);
            int h = n >> 6, dh = n & 63;
            float* op = outp + (size_t)h * ((size_t)NM * NDH);
            *(float2*)&op[(size_t)m * NDH + dh]       = make_float2(c[mt][nt][0], c[mt][nt][1]);
            *(float2*)&op[(size_t)(m + 8) * NDH + dh] = make_float2(c[mt][nt][2], c[mt][nt][3]);
        }
    }
}

// ---------------------------------------------------------------------------
// K2: scores (tf32 mma).  E[b,s,t] = exp( (q.k)/8 )
// Block 128x128, BK=32 (2 passes over d=64), warp tile 64x32.  grid (8,8,16).
// ---------------------------------------------------------------------------
__global__ void __launch_bounds__(256) k_scores(int h) {
    __shared__ __align__(16) uint32_t As[128 * 36];   // q tile [s][d]
    __shared__ __align__(16) uint32_t Bs[128 * 36];   // k tile [t][d]
    const int b  = blockIdx.z;
    const size_t base = ((size_t)h * NB + b) * NS * NDH;
    const float* qp = g_q + base;
    const float* kp = g_k + base;
    const int s0 = blockIdx.y * 128, t0 = blockIdx.x * 128;
    const int tid = threadIdx.x, lane = tid & 31, wid = tid >> 5;
    const int warp_m = (wid & 1) * 64, warp_n = (wid >> 1) * 32;
    const int xm = tid >> 3, xk = (tid & 7) * 4;
    float c[4][4][4] = {};

    for (int k0 = 0; k0 < NDH; k0 += 32) {
        #pragma unroll
        for (int l = 0; l < 4; l++) {
            int m = xm + l * 32;
            float4 qv = *(const float4*)&qp[(size_t)(s0 + m) * NDH + k0 + xk];
            *(uint4*)&As[m * 36 + xk] =
                make_uint4(cvt_tf32(qv.x), cvt_tf32(qv.y), cvt_tf32(qv.z), cvt_tf32(qv.w));
            float4 kv = *(const float4*)&kp[(size_t)(t0 + m) * NDH + k0 + xk];
            *(uint4*)&Bs[m * 36 + xk] =
                make_uint4(cvt_tf32(kv.x), cvt_tf32(kv.y), cvt_tf32(kv.z), cvt_tf32(kv.w));
        }
        __syncthreads();
        #pragma unroll
        for (int ks = 0; ks < 32; ks += 8) {
            uint32_t a[4][4], b2[4][2];
            #pragma unroll
            for (int mt = 0; mt < 4; mt++) ldA36(a[mt], As, warp_m + mt * 16, ks, lane);
            #pragma unroll
            for (int nt = 0; nt < 4; nt++) ldBnk36(b2[nt], Bs, warp_n + nt * 8, ks, lane);
            #pragma unroll
            for (int mt = 0; mt < 4; mt++)
                #pragma unroll
                for (int nt = 0; nt < 4; nt++) mma8(c[mt][nt], a[mt], b2[nt]);
        }
        __syncthreads();
    }
    float* ep = g_E + (size_t)b * NS * NS;
    #pragma unroll
    for (int mt = 0; mt < 4; mt++) {
        #pragma unroll
        for (int nt = 0; nt < 4; nt++) {
            int s = s0 + warp_m + mt * 16 + (lane >> 2);
            int t = t0 + warp_n + nt * 8 + 2 * (lane & 3);
            *(float2*)&ep[(size_t)s * NS + t] =
                make_float2(__expf(c[mt][nt][0] * 0.125f), __expf(c[mt][nt][1] * 0.125f));
            *(float2*)&ep[(size_t)(s + 8) * NS + t] =
                make_float2(__expf(c[mt][nt][2] * 0.125f), __expf(c[mt][nt][3] * 0.125f));
        }
    }
}

// ---------------------------------------------------------------------------
// K3: batch-axis denominator.  R[s,t] = 1 / sum_b E[b,s,t]   (float4)
// ---------------------------------------------------------------------------
__global__ void k_bsum() {
    int idx = blockIdx.x * 256 + threadIdx.x;   // over NS*NS/4
    const float4* ep = (const float4*)g_E + idx;
    float4 sum = make_float4(0.f, 0.f, 0.f, 0.f);
    #pragma unroll
    for (int b = 0; b < 16; b++) {
        float4 e = ep[(size_t)b * (NS * NS / 4)];
        sum.x += e.x; sum.y += e.y; sum.z += e.z; sum.w += e.w;
    }
    ((float4*)g_R)[idx] = make_float4(1.f / sum.x, 1.f / sum.y, 1.f / sum.z, 1.f / sum.w);
}

// ---------------------------------------------------------------------------
// K4: AV (tf32 mma), split-K x4.
// att[b,s,h*64+d] += sum_{t in chunk} (E*R)[b,s,t] * v[b,t,d]
// Block 128(s)x64(d), BK=32, 8 warps (4m x 2n), warp tile 32x32.
// grid (4 t-chunks, 8 s-tiles, 16 b).  atomicAdd accumulation.
// ---------------------------------------------------------------------------
__global__ void __launch_bounds__(256) k_av(int h) {
    __shared__ __align__(16) uint32_t As[128 * 36];   // (E*R) tile [s][t]
    __shared__ __align__(16) uint32_t Vs[32 * 68];    // v tile [t][d]
    const int b  = blockIdx.z;
    const int s0 = blockIdx.y * 128;
    const int tb = blockIdx.x * 256;
    const float* ep = g_E + (size_t)b * NS * NS;
    const float* vp = g_v + ((size_t)h * NB + b) * NS * NDH;
    const int tid = threadIdx.x, lane = tid & 31, wid = tid >> 5;
    const int warp_m = (wid & 3) * 32, warp_n = (wid >> 2) * 32;
    const int xm = tid >> 3, xk = (tid & 7) * 4;
    const int vt = tid >> 4, vs = (tid & 15) * 4;
    float c[2][4][4] = {};

    for (int t0 = tb; t0 < tb + 256; t0 += 32) {
        #pragma unroll
        for (int l = 0; l < 4; l++) {
            int m = xm + l * 32;
            size_t off = (size_t)(s0 + m) * NS + t0 + xk;
            float4 e = *(const float4*)&ep[off];
            float4 r = *(const float4*)&g_R[off];
            *(uint4*)&As[m * 36 + xk] =
                make_uint4(cvt_tf32(e.x * r.x), cvt_tf32(e.y * r.y),
                           cvt_tf32(e.z * r.z), cvt_tf32(e.w * r.w));
        }
        #pragma unroll
        for (int l = 0; l < 2; l++) {
            int t = vt + l * 16;
            float4 v = *(const float4*)&vp[(size_t)(t0 + t) * NDH + vs];
            *(uint4*)&Vs[t * 68 + vs] =
                make_uint4(cvt_tf32(v.x), cvt_tf32(v.y), cvt_tf32(v.z), cvt_tf32(v.w));
        }
        __syncthreads();
        #pragma unroll
        for (int ks = 0; ks < 32; ks += 8) {
            uint32_t a[2][4], b2[4][2];
            #pragma unroll
            for (int mt = 0; mt < 2; mt++) ldA36(a[mt], As, warp_m + mt * 16, ks, lane);
            #pragma unroll
            for (int nt = 0; nt < 4; nt++) ldBkn(b2[nt], Vs, 68, warp_n + nt * 8, ks, lane);
            #pragma unroll
            for (int mt = 0; mt < 2; mt++)
                #pragma unroll
                for (int nt = 0; nt < 4; nt++) mma8(c[mt][nt], a[mt], b2[nt]);
        }
        __syncthreads();
    }
    #pragma unroll
    for (int mt = 0; mt < 2; mt++) {
        #pragma unroll
        for (int nt = 0; nt < 4; nt++) {
            int s = s0 + warp_m + mt * 16 + (lane >> 2);
            int d = warp_n + nt * 8 + 2 * (lane & 3);
            float* dst0 = &g_att[(size_t)(b * NS + s) * NOUT + h * 64 + d];
            float* dst1 = &g_att[(size_t)(b * NS + s + 8) * NOUT + h * 64 + d];
            atomicAdd(dst0 + 0, c[mt][nt][0]);
            atomicAdd(dst0 + 1, c[mt][nt][1]);
            atomicAdd(dst1 + 0, c[mt][nt][2]);
            atomicAdd(dst1 + 1, c[mt][nt][3]);
        }
    }
}

// ---------------------------------------------------------------------------
// K5: output projection (tf32 mma).  y = att @ w_out + b_out (y into g_E)
// Block 128x128, BK=32, warp tile 64x32.  grid (4,128).
// ---------------------------------------------------------------------------
__global__ void __launch_bounds__(256) k_proj(const float* __restrict__ w,
                                              const float* __restrict__ bias) {
    __shared__ __align__(16) uint32_t As[128 * 36];   // att tile [m][k]
    __shared__ __align__(16) uint32_t Bs[32 * 132];   // w tile   [k][n]
    const int m0 = blockIdx.y * 128, n0 = blockIdx.x * 128;
    const int tid = threadIdx.x, lane = tid & 31, wid = tid >> 5;
    const int warp_m = (wid & 1) * 64, warp_n = (wid >> 1) * 32;
    const int xm = tid >> 3, xk = (tid & 7) * 4;
    const int n4 = tid & 31, kw = tid >> 5;
    float c[4][4][4] = {};

    for (int k0 = 0; k0 < NOUT; k0 += 32) {
        #pragma unroll
        for (int l = 0; l < 4; l++) {
            int m = xm + l * 32;
            float4 v = *(const float4*)&g_att[(size_t)(m0 + m) * NOUT + k0 + xk];
            *(uint4*)&As[m * 36 + xk] =
                make_uint4(cvt_tf32(v.x), cvt_tf32(v.y), cvt_tf32(v.z), cvt_tf32(v.w));
        }
        #pragma unroll
        for (int l = 0; l < 4; l++) {
            int kk = kw + l * 8;
            float4 v = *(const float4*)&w[(size_t)(k0 + kk) * NOUT + n0 + n4 * 4];
            *(uint4*)&Bs[kk * 132 + n4 * 4] =
                make_uint4(cvt_tf32(v.x), cvt_tf32(v.y), cvt_tf32(v.z), cvt_tf32(v.w));
        }
        __syncthreads();
        #pragma unroll
        for (int ks = 0; ks < 32; ks += 8) {
            uint32_t a[4][4], b2[4][2];
            #pragma unroll
            for (int mt = 0; mt < 4; mt++) ldA36(a[mt], As, warp_m + mt * 16, ks, lane);
            #pragma unroll
            for (int nt = 0; nt < 4; nt++) ldBkn(b2[nt], Bs, 132, warp_n + nt * 8, ks, lane);
            #pragma unroll
            for (int mt = 0; mt < 4; mt++)
                #pragma unroll
                for (int nt = 0; nt < 4; nt++) mma8(c[mt][nt], a[mt], b2[nt]);
        }
        __syncthreads();
    }
    float* yp = g_E;   // reuse g_E as pre-LN output
    #pragma unroll
    for (int mt = 0; mt < 4; mt++) {
        #pragma unroll
        for (int nt = 0; nt < 4; nt++) {
            int m = m0 + warp_m + mt * 16 + (lane >> 2);
            int n = n0 + warp_n + nt * 8 + 2 * (lane & 3);
            float b0 = bias[n], b1 = bias[n + 1];
            *(float2*)&yp[(size_t)m * NOUT + n] =
                make_float2(c[mt][nt][0] + b0, c[mt][nt][1] + b1);
            *(float2*)&yp[(size_t)(m + 8) * NOUT + n] =
                make_float2(c[mt][nt][2] + b0, c[mt][nt][3] + b1);
        }
    }
}

// ---------------------------------------------------------------------------
// K6: LayerNorm + LeakyReLU(0.1).  One block per row (reads y from g_E).
// ---------------------------------------------------------------------------
__global__ void k_ln(const float* __restrict__ gamma, const float* __restrict__ beta,
                     float* __restrict__ out) {
    const int row = blockIdx.x;
    const float* yp = g_E + (size_t)row * NOUT;
    const int tid = threadIdx.x;
    float v0 = yp[tid], v1 = yp[tid + 256];
    float s = v0 + v1, sq = v0 * v0 + v1 * v1;

    __shared__ float red[8], red2[8], stat[2];
    #pragma unroll
    for (int o = 16; o > 0; o >>= 1) {
        s  += __shfl_xor_sync(0xFFFFFFFFu, s,  o);
        sq += __shfl_xor_sync(0xFFFFFFFFu, sq, o);
    }
    int wid = tid >> 5, lane = tid & 31;
    if (lane == 0) { red[wid] = s; red2[wid] = sq; }
    __syncthreads();
    if (tid == 0) {
        float S = 0.f, Q = 0.f;
        #pragma unroll
        for (int i = 0; i < 8; i++) { S += red[i]; Q += red2[i]; }
        float mu  = S * (1.0f / NOUT);
        float var = Q * (1.0f / NOUT) - mu * mu;
        stat[0] = mu;
        stat[1] = rsqrtf(var + 1e-5f);
    }
    __syncthreads();
    float mu = stat[0], rv = stat[1];

    float t0 = (v0 - mu) * rv * gamma[tid]       + beta[tid];
    float t1 = (v1 - mu) * rv * gamma[tid + 256] + beta[tid + 256];
    t0 = t0 >= 0.f ? t0 : 0.1f * t0;
    t1 = t1 >= 0.f ? t1 : 0.1f * t1;
    out[(size_t)row * NOUT + tid]       = t0;
    out[(size_t)row * NOUT + tid + 256] = t1;
}

// ---------------------------------------------------------------------------
extern "C" void kernel_launch(void* const* d_in, const int* in_sizes, int n_in,
                              void* d_out, int out_size) {
    const float* x     = (const float*)d_in[0];
    const float* wq    = (const float*)d_in[1];
    const float* wk    = (const float*)d_in[2];
    const float* wv    = (const float*)d_in[3];
    const float* w_out = (const float*)d_in[4];
    const float* b_out = (const float*)d_in[5];
    const float* gamma = (const float*)d_in[6];
    const float* beta  = (const float*)d_in[7];
    float* out = (float*)d_out;

    k_zero<<<(NM * NOUT / 4) / 256, 256>>>();
    k_qkv <<<dim3(NOUT / 128, NM / 128, 3), 256>>>(x, wq, wk, wv);

    for (int h = 0; h < NH; h++) {
        k_scores<<<dim3(NS / 128, NS / 128, NB), 256>>>(h);
        k_bsum  <<<(NS * NS / 4) / 256, 256>>>();
        k_av    <<<dim3(4, NS / 128, NB), 256>>>(h);
    }

    k_proj<<<dim3(NOUT / 128, NM / 128), 256>>>(w_out, b_out);
    k_ln  <<<NM, 256>>>(gamma, beta, out);
}